// round 14
// baseline (speedup 1.0000x reference)
#include <cuda_runtime.h>
#include <cuda_fp16.h>
#include <math.h>
#include <stdint.h>

#define B_  4
#define S_  2048
#define D_  1024
#define H_  16
#define HD_ 64
#define K_  1024

// fp16 intermediates
__device__ __align__(16) __half g_Kh[B_*H_*S_*HD_];   // [b][h][s][d]
__device__ __align__(16) __half g_Vt[B_*H_*HD_*S_];   // [b][h][d][s]  (transposed)
__device__ __align__(16) __half g_Qh[B_*H_*S_*HD_];   // [b][h][s][d]
__device__ __align__(16) __half g_ctx[B_*S_*D_];      // attention out (fp16)

// fp16 activations (single) + fp16 hi/lo weights (transposed [N][K])
__device__ __align__(16) __half g_xf[B_*S_*D_], g_yf[B_*S_*D_];
__device__ __align__(16) __half g_Wkvh[2*D_*D_], g_Wkvl[2*D_*D_];
__device__ __align__(16) __half g_Wqh[D_*D_],  g_Wql[D_*D_];
__device__ __align__(16) __half g_Woh[D_*D_],  g_Wol[D_*D_];

// ---------------------------------------------------------------------------
// helpers
// ---------------------------------------------------------------------------
__device__ __forceinline__ uint32_t smem_u32(const void* p) {
    uint32_t a;
    asm("{ .reg .u64 t; cvta.to.shared.u64 t, %1; cvt.u32.u64 %0, t; }" : "=r"(a) : "l"(p));
    return a;
}
__device__ __forceinline__ void cp16(void* dst, const void* src) {
    uint32_t d = smem_u32(dst);
    asm volatile("cp.async.cg.shared.global [%0], [%1], 16;" :: "r"(d), "l"(src) : "memory");
}
#define CP_COMMIT() asm volatile("cp.async.commit_group;" ::: "memory")
#define CP_WAIT(n)  asm volatile("cp.async.wait_group %0;" :: "n"(n) : "memory")

// ldmatrix x4
__device__ __forceinline__ void ldsm4(unsigned& r0, unsigned& r1,
                                      unsigned& r2, unsigned& r3, uint32_t addr)
{
    asm volatile("ldmatrix.sync.aligned.m8n8.x4.shared.b16 {%0,%1,%2,%3}, [%4];"
        : "=r"(r0), "=r"(r1), "=r"(r2), "=r"(r3) : "r"(addr));
}

// fp16 mma
__device__ __forceinline__ void mma16h(float4& d,
    unsigned a0, unsigned a1, unsigned a2, unsigned a3, unsigned b0, unsigned b1)
{
    asm volatile("mma.sync.aligned.m16n8k16.row.col.f32.f16.f16.f32 "
        "{%0,%1,%2,%3},{%4,%5,%6,%7},{%8,%9},{%0,%1,%2,%3};\n"
        : "+f"(d.x), "+f"(d.y), "+f"(d.z), "+f"(d.w)
        : "r"(a0), "r"(a1), "r"(a2), "r"(a3), "r"(b0), "r"(b1));
}
// FFMA-pipe exp
__device__ __forceinline__ float fast_exp(float x) {
    float t = x * 1.4426950408889634f;
    t = fmaxf(t, -126.0f);
    float z = t + 12582912.0f;
    int   n = __float_as_int(z) - 0x4B400000;
    float f = t - (z - 12582912.0f);
    float p = 1.3333558146e-3f;
    p = fmaf(p, f, 9.6181291976e-3f);
    p = fmaf(p, f, 5.5504108664e-2f);
    p = fmaf(p, f, 2.4022650695e-1f);
    p = fmaf(p, f, 6.9314718056e-1f);
    p = fmaf(p, f, 1.0f);
    return __int_as_float(__float_as_int(p) + (n << 23));
}

// ---------------------------------------------------------------------------
// converts: fp32 -> fp16 (activations), fp32 W[K][N] -> fp16 hi/lo [N][K]
// ---------------------------------------------------------------------------
__global__ void __launch_bounds__(256) to_half(const float* __restrict__ src,
    __half* __restrict__ dst, int n4)
{
    int i = blockIdx.x * 256 + threadIdx.x;
    if (i >= n4) return;
    float4 v = ((const float4*)src)[i];
    __half2 h01 = __floats2half2_rn(v.x, v.y);
    __half2 h23 = __floats2half2_rn(v.z, v.w);
    uint2 hv = { *(unsigned*)&h01, *(unsigned*)&h23 };
    *(uint2*)(dst + 4 * (size_t)i) = hv;
}

__global__ void __launch_bounds__(256) split_transpose_h(const float* __restrict__ W,
    __half* __restrict__ th, __half* __restrict__ tl, int Kd, int Nd)
{
    int n  = blockIdx.x * 32 + (threadIdx.x & 31);
    int k0 = blockIdx.y * 64 + (threadIdx.x >> 5) * 8;
    __half hh[8], ll[8];
    #pragma unroll
    for (int j = 0; j < 8; j++) {
        float v = W[(size_t)(k0 + j) * Nd + n];
        __half hb = __float2half_rn(v);
        hh[j] = hb;
        ll[j] = __float2half_rn(v - __half2float(hb));
    }
    *(uint4*)(th + (size_t)n * Kd + k0) = *(uint4*)hh;
    *(uint4*)(tl + (size_t)n * Kd + k0) = *(uint4*)ll;
}

// ---------------------------------------------------------------------------
// fp16 B-split GEMM: C = A_fp16 @ (Wh + Wl)^T + bias, 2 MMAs per k16 tile.
// BM=128 BN=64 BK=32, 8 warps, 3-stage cp.async pipeline, LDSM fragments.
// Row stride 80B. 61.4KB smem -> 2 CTA/SM.  (R12-proven configuration)
// ---------------------------------------------------------------------------
extern __shared__ char dynsm[];

#define G2BUF 20480
#define A2    0
#define B2H   10240
#define B2L   15360

template<int MODE>
__global__ void __launch_bounds__(256, 2) gemm_fp16(
    const __half* __restrict__ A, const __half* __restrict__ Bh,
    const __half* __restrict__ Bl, const float* __restrict__ bias,
    float* __restrict__ out, int Ntot)
{
    const int tid = threadIdx.x, lane = tid & 31, warp = tid >> 5;
    const int wm = (warp >> 1) * 32, wn = (warp & 1) * 32;
    const int m0 = blockIdx.y * 128, n0 = blockIdx.x * 64;

    const __half* ag  = A  + (size_t)m0 * K_;
    const __half* bgh = Bh + (size_t)n0 * K_;
    const __half* bgl = Bl + (size_t)n0 * K_;

    const int ra = tid >> 1, ga = tid & 1;
    const int t2 = tid & 127;
    const int rb = t2 >> 1, gb = t2 & 1;
    const __half* bsrc = (tid < 128) ? bgh : bgl;
    const int bofs = (tid < 128) ? B2H : B2L;

    auto issue_loads = [&](int kc, int buf) {
        char* bb = dynsm + buf * G2BUF;
        const __half* sa = ag + (size_t)ra * K_ + kc * 32 + ga * 16;
        const __half* sb = bsrc + (size_t)rb * K_ + kc * 32 + gb * 16;
        cp16(bb + A2 + ra * 80 + ga * 32,      sa);
        cp16(bb + A2 + ra * 80 + ga * 32 + 16, sa + 8);
        cp16(bb + bofs + rb * 80 + gb * 32,      sb);
        cp16(bb + bofs + rb * 80 + gb * 32 + 16, sb + 8);
    };

    float4 acc[2][4];
    #pragma unroll
    for (int mt = 0; mt < 2; mt++)
        #pragma unroll
        for (int nt = 0; nt < 4; nt++) acc[mt][nt] = make_float4(0.f, 0.f, 0.f, 0.f);

    issue_loads(0, 0); CP_COMMIT();
    issue_loads(1, 1); CP_COMMIT();

    const uint32_t smb = smem_u32(dynsm);
    const uint32_t a_off = (uint32_t)(lane & 15) * 80 + 16 * (lane >> 4);
    const uint32_t b_off = (uint32_t)(8 * (lane >> 4) + (lane & 7)) * 80
                         + 16 * ((lane >> 3) & 1);

    #pragma unroll 1
    for (int kc = 0; kc < 32; kc++) {
        if (kc < 31) CP_WAIT(1); else CP_WAIT(0);
        __syncthreads();
        if (kc + 2 < 32) { issue_loads(kc + 2, (kc + 2) % 3); CP_COMMIT(); }

        const uint32_t bufb = smb + (kc % 3) * G2BUF;
        #pragma unroll
        for (int ks = 0; ks < 2; ks++) {
            const uint32_t kso = ks * 32;
            unsigned a[2][4];
            #pragma unroll
            for (int mt = 0; mt < 2; mt++)
                ldsm4(a[mt][0], a[mt][1], a[mt][2], a[mt][3],
                      bufb + A2 + (uint32_t)(wm + mt * 16) * 80 + a_off + kso);
            #pragma unroll
            for (int ntp = 0; ntp < 2; ntp++) {
                const uint32_t nrow = (uint32_t)(wn + 16 * ntp) * 80 + b_off + kso;
                unsigned h0, h1, h2, h3, l0, l1, l2, l3;
                ldsm4(h0, h1, h2, h3, bufb + B2H + nrow);
                ldsm4(l0, l1, l2, l3, bufb + B2L + nrow);
                #pragma unroll
                for (int mt = 0; mt < 2; mt++) {
                    mma16h(acc[mt][2*ntp],   a[mt][0], a[mt][1], a[mt][2], a[mt][3], h0, h1);
                    mma16h(acc[mt][2*ntp],   a[mt][0], a[mt][1], a[mt][2], a[mt][3], l0, l1);
                    mma16h(acc[mt][2*ntp+1], a[mt][0], a[mt][1], a[mt][2], a[mt][3], h2, h3);
                    mma16h(acc[mt][2*ntp+1], a[mt][0], a[mt][1], a[mt][2], a[mt][3], l2, l3);
                }
            }
        }
    }

    // ---- epilogue ----
    const int r = lane >> 2, q = lane & 3;
    #pragma unroll
    for (int mt = 0; mt < 2; mt++) {
        #pragma unroll
        for (int nt = 0; nt < 4; nt++) {
            int mg = m0 + wm + mt * 16 + r;
            int ng = n0 + wn + nt * 8 + 2 * q;
            float bv0 = bias[ng], bv1 = bias[ng + 1];
            float2 v0 = {acc[mt][nt].x + bv0, acc[mt][nt].y + bv1};
            float2 v1 = {acc[mt][nt].z + bv0, acc[mt][nt].w + bv1};
            #pragma unroll
            for (int rr = 0; rr < 2; rr++) {
                int m = mg + rr * 8;
                float2 v = rr ? v1 : v0;
                if (MODE == 0) {
                    int bi = m >> 11, s = m & (S_-1);
                    int h = ng >> 7, c = ng & 127;
                    if (c < 64) {
                        __half2 hv = __floats2half2_rn(v.x, v.y);
                        *(__half2*)(g_Kh + (((size_t)(bi*H_ + h) * S_ + s) * HD_ + c)) = hv;
                    } else {
                        int d = c - 64;
                        size_t base = ((size_t)(bi*H_ + h) * HD_ + d) * S_ + s;
                        g_Vt[base]      = __float2half_rn(v.x);
                        g_Vt[base + S_] = __float2half_rn(v.y);
                    }
                } else if (MODE == 1) {
                    int bi = m >> 11, s = m & (S_-1);
                    int h = ng >> 6, d = ng & 63;
                    __half2 hv = __floats2half2_rn(v.x, v.y);
                    *(__half2*)(g_Qh + (((size_t)(bi*H_ + h) * S_ + s) * HD_ + d)) = hv;
                } else {
                    *(float2*)(out + (size_t)m * Ntot + ng) = v;
                }
            }
        }
    }
}

// ---------------------------------------------------------------------------
// Flash attention, fp16 m16n8k16, fixed-shift softmax.
// R14: R12 base + Q fragments hoisted to registers + 3-buffer K/V pipeline
// (issue-2-ahead, CP_WAIT(1)). fp32 mask in registers. 128-row q tiles,
// 8 warps, 2 CTAs/SM (64.5KB smem).
// ---------------------------------------------------------------------------
#define SQH 72
#define SKH 72
#define SVH 72

__global__ void __launch_bounds__(256, 2) attn_fp16(
    const __half* __restrict__ gK, const __half* __restrict__ gVt,
    const __half* __restrict__ gQ, const float* __restrict__ mask,
    __half* __restrict__ ctx)
{
    __half* smh = (__half*)dynsm;
    __half* Qs  = smh;                      // [128][SQH]
    __half* Kb  = Qs + 128 * SQH;           // 3 x [64][SKH]
    __half* Vb  = Kb + 3 * 64 * SKH;        // 3 x [64][SVH]

    const int tid  = threadIdx.x;
    const int lane = tid & 31;
    const int w    = tid >> 5;
    const int ib   = w * 16;
    const int q0   = blockIdx.x * 128;
    const int h    = blockIdx.y;
    const int b    = blockIdx.z;

    const __half* Qg = gQ  + ((size_t)(b*H_ + h) * S_ + q0) * HD_;
    const __half* Kg = gK  + ((size_t)(b*H_ + h) * S_) * HD_;
    const __half* Vg = gVt + ((size_t)(b*H_ + h) * HD_) * S_;

    // Q tile -> smem (its own cp.async group)
    {
        int r = tid >> 1, cs = (tid & 1) * 32;
        const __half* src = Qg + (size_t)r * HD_ + cs;
        __half* dst = Qs + r * SQH + cs;
        cp16(dst,      src);
        cp16(dst + 8,  src + 8);
        cp16(dst + 16, src + 16);
        cp16(dst + 24, src + 24);
    }
    CP_COMMIT();

    const int rKV = tid >> 2;
    const int seg = (tid & 3) * 16;

    auto issue = [&](int kt, int buf) {
        __half* Kd = Kb + buf * 64 * SKH;
        __half* Vd = Vb + buf * 64 * SVH;
        const __half* ks = Kg + (size_t)(kt*64 + rKV) * HD_ + seg;
        const __half* vs = Vg + (size_t)rKV * S_ + kt*64 + seg;
        cp16(Kd + rKV * SKH + seg,     ks);
        cp16(Kd + rKV * SKH + seg + 8, ks + 8);
        cp16(Vd + rKV * SVH + seg,     vs);
        cp16(Vd + rKV * SVH + seg + 8, vs + 8);
    };

    issue(0, 0); CP_COMMIT();
    issue(1, 1); CP_COMMIT();

    float4 o[8];
    #pragma unroll
    for (int nt = 0; nt < 8; nt++) o[nt] = make_float4(0.f, 0.f, 0.f, 0.f);
    float l0r = 0.f, l1r = 0.f;

    const int r  = lane >> 2;
    const int qd = lane & 3;
    const int grow0 = ib + r;
    const int grow1 = grow0 + 8;
    const float* mrow0 = mask + (size_t)(q0 + grow0) * S_ + 2 * qd;
    const float* mrow1 = mask + (size_t)(q0 + grow1) * S_ + 2 * qd;

    // LDSM per-lane byte offsets
    const uint32_t qs_b = smem_u32(Qs);
    const uint32_t kb_b = smem_u32(Kb);
    const uint32_t vb_b = smem_u32(Vb);
    const uint32_t q_off = ((uint32_t)(ib + (lane & 15)) * SQH) * 2 + 16 * (lane >> 4);
    const uint32_t k_row = ((uint32_t)(8 * (lane >> 4) + (lane & 7)) * SKH) * 2
                         + 16 * ((lane >> 3) & 1);
    const uint32_t v_row = ((uint32_t)(8 * (lane >> 4) + (lane & 7)) * SVH) * 2
                         + 16 * ((lane >> 3) & 1);

    // hoist Q fragments into registers (loop-invariant)
    CP_WAIT(2);            // Q group complete (kt0, kt1 groups may be outstanding)
    __syncthreads();
    unsigned qa[4][4];
    #pragma unroll
    for (int kc = 0; kc < 4; kc++)
        ldsm4(qa[kc][0], qa[kc][1], qa[kc][2], qa[kc][3], qs_b + q_off + 32 * kc);

    #pragma unroll 1
    for (int kt = 0; kt < S_/64; kt++) {
        if (kt < 31) CP_WAIT(1); else CP_WAIT(0);
        __syncthreads();
        if (kt + 2 < S_/64) { issue(kt + 2, (kt + 2) % 3); CP_COMMIT(); }

        // prefetch fp32 mask into registers (hidden under QK mma)
        float2 mreg[16];
        #pragma unroll
        for (int nt = 0; nt < 8; nt++) {
            mreg[2*nt]   = *(const float2*)(mrow0 + kt * 64 + nt * 8);
            mreg[2*nt+1] = *(const float2*)(mrow1 + kt * 64 + nt * 8);
        }

        const int cur = kt % 3;
        const uint32_t ksb = kb_b + cur * (64 * SKH * 2);
        const uint32_t vsb = vb_b + cur * (64 * SVH * 2);

        // --- S = Q K^T ---
        float4 s[8];
        #pragma unroll
        for (int nt = 0; nt < 8; nt++) s[nt] = make_float4(0.f, 0.f, 0.f, 0.f);
        #pragma unroll
        for (int kc = 0; kc < 4; kc++) {
            #pragma unroll
            for (int ntp = 0; ntp < 4; ntp++) {
                unsigned b0, b1, b2, b3;
                ldsm4(b0, b1, b2, b3,
                      ksb + (uint32_t)(16 * ntp) * (SKH * 2) + k_row + 32 * kc);
                mma16h(s[2*ntp],   qa[kc][0], qa[kc][1], qa[kc][2], qa[kc][3], b0, b1);
                mma16h(s[2*ntp+1], qa[kc][0], qa[kc][1], qa[kc][2], qa[kc][3], b2, b3);
            }
        }

        // --- fixed-shift softmax; pack P into A-fragment registers ---
        unsigned pa0[8], pa1[8];
        #pragma unroll
        for (int nt = 0; nt < 8; nt++) {
            float p00 = fast_exp(fmaf(s[nt].x, 0.125f, mreg[2*nt].x));
            float p01 = fast_exp(fmaf(s[nt].y, 0.125f, mreg[2*nt].y));
            float p10 = fast_exp(fmaf(s[nt].z, 0.125f, mreg[2*nt+1].x));
            float p11 = fast_exp(fmaf(s[nt].w, 0.125f, mreg[2*nt+1].y));
            l0r += p00 + p01;
            l1r += p10 + p11;
            __half2 h0 = __floats2half2_rn(p00, p01);
            __half2 h1 = __floats2half2_rn(p10, p11);
            pa0[nt] = *(unsigned*)&h0;
            pa1[nt] = *(unsigned*)&h1;
        }

        // --- O += P V ---
        #pragma unroll
        for (int kc = 0; kc < 4; kc++) {
            unsigned a0 = pa0[2*kc];
            unsigned a1 = pa1[2*kc];
            unsigned a2 = pa0[2*kc + 1];
            unsigned a3 = pa1[2*kc + 1];
            #pragma unroll
            for (int ntp = 0; ntp < 4; ntp++) {
                unsigned b0, b1, b2, b3;
                ldsm4(b0, b1, b2, b3,
                      vsb + (uint32_t)(16 * ntp) * (SVH * 2) + v_row + 32 * kc);
                mma16h(o[2*ntp],   a0, a1, a2, a3, b0, b1);
                mma16h(o[2*ntp+1], a0, a1, a2, a3, b2, b3);
            }
        }
    }

    // row-sum reduction + normalize + fp16 ctx store
    l0r += __shfl_xor_sync(0xffffffffu, l0r, 1);
    l0r += __shfl_xor_sync(0xffffffffu, l0r, 2);
    l1r += __shfl_xor_sync(0xffffffffu, l1r, 1);
    l1r += __shfl_xor_sync(0xffffffffu, l1r, 2);
    float inv0 = 1.f / l0r;
    float inv1 = 1.f / l1r;
    int gq = q0 + grow0;
    #pragma unroll
    for (int nt = 0; nt < 8; nt++) {
        int dcol = h * HD_ + nt * 8 + 2 * qd;
        size_t i0 = ((size_t)b * S_ + gq) * D_ + dcol;
        size_t i1 = ((size_t)b * S_ + gq + 8) * D_ + dcol;
        __half2 h0 = __floats2half2_rn(o[nt].x * inv0, o[nt].y * inv0);
        __half2 h1 = __floats2half2_rn(o[nt].z * inv1, o[nt].w * inv1);
        *(__half2*)&ctx[i0] = h0;
        *(__half2*)&ctx[i1] = h1;
    }
}

// ---------------------------------------------------------------------------
extern "C" void kernel_launch(void* const* d_in, const int* in_sizes, int n_in,
                              void* d_out, int out_size)
{
    const float* x    = (const float*)d_in[0];
    const float* y    = (const float*)d_in[1];
    const float* mask = (const float*)d_in[2];
    const float* Wkv  = (const float*)d_in[3];
    const float* bkv  = (const float*)d_in[4];
    const float* Wq   = (const float*)d_in[5];
    const float* bq   = (const float*)d_in[6];
    const float* Wo   = (const float*)d_in[7];
    const float* bo   = (const float*)d_in[8];
    float* out = (float*)d_out;

    __half *pKh, *pVt, *pQh, *pCtx, *pxf, *pyf;
    __half *pWkvh, *pWkvl, *pWqh, *pWql, *pWoh, *pWol;
    cudaGetSymbolAddress((void**)&pKh, g_Kh);
    cudaGetSymbolAddress((void**)&pVt, g_Vt);
    cudaGetSymbolAddress((void**)&pQh, g_Qh);
    cudaGetSymbolAddress((void**)&pCtx, g_ctx);
    cudaGetSymbolAddress((void**)&pxf, g_xf);
    cudaGetSymbolAddress((void**)&pyf, g_yf);
    cudaGetSymbolAddress((void**)&pWkvh, g_Wkvh); cudaGetSymbolAddress((void**)&pWkvl, g_Wkvl);
    cudaGetSymbolAddress((void**)&pWqh, g_Wqh);   cudaGetSymbolAddress((void**)&pWql, g_Wql);
    cudaGetSymbolAddress((void**)&pWoh, g_Woh);   cudaGetSymbolAddress((void**)&pWol, g_Wol);

    const int GSM = 3 * G2BUF;                                  // 61440 B
    const int ASM = (128*SQH + 3*64*SKH + 3*64*SVH) * 2;        // 73728 B -> with Qs: 66048? computed below
    cudaFuncSetAttribute(gemm_fp16<0>, cudaFuncAttributeMaxDynamicSharedMemorySize, GSM);
    cudaFuncSetAttribute(gemm_fp16<1>, cudaFuncAttributeMaxDynamicSharedMemorySize, GSM);
    cudaFuncSetAttribute(gemm_fp16<2>, cudaFuncAttributeMaxDynamicSharedMemorySize, GSM);
    cudaFuncSetAttribute(attn_fp16, cudaFuncAttributeMaxDynamicSharedMemorySize, ASM);

    const int NE4 = B_ * S_ * D_ / 4;

    // 1. converts / weight splits
    to_half<<<(NE4 + 255) / 256, 256>>>(x, pxf, NE4);
    to_half<<<(NE4 + 255) / 256, 256>>>(y, pyf, NE4);
    split_transpose_h<<<dim3(2*D_/32, K_/64), 256>>>(Wkv, pWkvh, pWkvl, K_, 2*D_);
    split_transpose_h<<<dim3(D_/32,   K_/64), 256>>>(Wq,  pWqh,  pWql,  K_, D_);
    split_transpose_h<<<dim3(D_/32,   K_/64), 256>>>(Wo,  pWoh,  pWol,  K_, D_);
    // 2. KV projection: M=8192, N=2048
    gemm_fp16<0><<<dim3(2048/64, 8192/128), 256, GSM>>>(pxf, pWkvh, pWkvl, bkv, nullptr, 2*D_);
    // 3. Q projection: M=8192, N=1024
    gemm_fp16<1><<<dim3(1024/64, 8192/128), 256, GSM>>>(pyf, pWqh, pWql, bq, nullptr, D_);
    // 4. attention (fp32 mask; writes fp16 ctx)
    attn_fp16<<<dim3(S_/128, H_, B_), 256, ASM>>>(pKh, pVt, pQh, mask, pCtx);
    // 5. O projection: M=8192, N=1024
    gemm_fp16<2><<<dim3(1024/64, 8192/128), 256, GSM>>>(pCtx, pWoh, pWol, bo, out, D_);
}

// round 15
// speedup vs baseline: 1.0476x; 1.0476x over previous
#include <cuda_runtime.h>
#include <cuda_fp16.h>
#include <math.h>
#include <stdint.h>

#define B_  4
#define S_  2048
#define D_  1024
#define H_  16
#define HD_ 64
#define K_  1024

// Q pre-scale: 0.125 * log2(e)  (folded softmax scale + base-2 conversion)
#define QSCALE 0.18033688011112042f
// mask pre-scale: log2(e)
#define MSCALE 1.4426950408889634f

// fp16 intermediates
__device__ __align__(16) __half g_Kh[B_*H_*S_*HD_];   // [b][h][s][d]
__device__ __align__(16) __half g_Vt[B_*H_*HD_*S_];   // [b][h][d][s]  (transposed)
__device__ __align__(16) __half g_Qh[B_*H_*S_*HD_];   // [b][h][s][d]  (pre-scaled)
__device__ __align__(16) __half g_ctx[B_*S_*D_];      // attention out (fp16)
__device__ __align__(16) float  g_msc[S_*S_];         // mask * log2(e), fp32

// fp16 activations (single) + fp16 hi/lo weights (transposed [N][K])
__device__ __align__(16) __half g_xf[B_*S_*D_], g_yf[B_*S_*D_];
__device__ __align__(16) __half g_Wkvh[2*D_*D_], g_Wkvl[2*D_*D_];
__device__ __align__(16) __half g_Wqh[D_*D_],  g_Wql[D_*D_];
__device__ __align__(16) __half g_Woh[D_*D_],  g_Wol[D_*D_];

// ---------------------------------------------------------------------------
// helpers
// ---------------------------------------------------------------------------
__device__ __forceinline__ uint32_t smem_u32(const void* p) {
    uint32_t a;
    asm("{ .reg .u64 t; cvta.to.shared.u64 t, %1; cvt.u32.u64 %0, t; }" : "=r"(a) : "l"(p));
    return a;
}
__device__ __forceinline__ void cp16(void* dst, const void* src) {
    uint32_t d = smem_u32(dst);
    asm volatile("cp.async.cg.shared.global [%0], [%1], 16;" :: "r"(d), "l"(src) : "memory");
}
#define CP_COMMIT() asm volatile("cp.async.commit_group;" ::: "memory")
#define CP_WAIT(n)  asm volatile("cp.async.wait_group %0;" :: "n"(n) : "memory")

// ldmatrix x4
__device__ __forceinline__ void ldsm4(unsigned& r0, unsigned& r1,
                                      unsigned& r2, unsigned& r3, uint32_t addr)
{
    asm volatile("ldmatrix.sync.aligned.m8n8.x4.shared.b16 {%0,%1,%2,%3}, [%4];"
        : "=r"(r0), "=r"(r1), "=r"(r2), "=r"(r3) : "r"(addr));
}

// fp16 mma
__device__ __forceinline__ void mma16h(float4& d,
    unsigned a0, unsigned a1, unsigned a2, unsigned a3, unsigned b0, unsigned b1)
{
    asm volatile("mma.sync.aligned.m16n8k16.row.col.f32.f16.f16.f32 "
        "{%0,%1,%2,%3},{%4,%5,%6,%7},{%8,%9},{%0,%1,%2,%3};\n"
        : "+f"(d.x), "+f"(d.y), "+f"(d.z), "+f"(d.w)
        : "r"(a0), "r"(a1), "r"(a2), "r"(a3), "r"(b0), "r"(b1));
}
// MUFU exp2 (inputs already in base-2 domain)
__device__ __forceinline__ float ex2(float x) {
    float r;
    asm("ex2.approx.f32 %0, %1;" : "=f"(r) : "f"(x));
    return r;
}

// ---------------------------------------------------------------------------
// converts
// ---------------------------------------------------------------------------
__global__ void __launch_bounds__(256) to_half(const float* __restrict__ src,
    __half* __restrict__ dst, int n4)
{
    int i = blockIdx.x * 256 + threadIdx.x;
    if (i >= n4) return;
    float4 v = ((const float4*)src)[i];
    __half2 h01 = __floats2half2_rn(v.x, v.y);
    __half2 h23 = __floats2half2_rn(v.z, v.w);
    uint2 hv = { *(unsigned*)&h01, *(unsigned*)&h23 };
    *(uint2*)(dst + 4 * (size_t)i) = hv;
}

__global__ void __launch_bounds__(256) scale_mask(const float* __restrict__ src,
    float* __restrict__ dst, int n4)
{
    int i = blockIdx.x * 256 + threadIdx.x;
    if (i >= n4) return;
    float4 v = ((const float4*)src)[i];
    v.x *= MSCALE; v.y *= MSCALE; v.z *= MSCALE; v.w *= MSCALE;
    ((float4*)dst)[i] = v;
}

__global__ void __launch_bounds__(256) split_transpose_h(const float* __restrict__ W,
    __half* __restrict__ th, __half* __restrict__ tl, int Kd, int Nd)
{
    int n  = blockIdx.x * 32 + (threadIdx.x & 31);
    int k0 = blockIdx.y * 64 + (threadIdx.x >> 5) * 8;
    __half hh[8], ll[8];
    #pragma unroll
    for (int j = 0; j < 8; j++) {
        float v = W[(size_t)(k0 + j) * Nd + n];
        __half hb = __float2half_rn(v);
        hh[j] = hb;
        ll[j] = __float2half_rn(v - __half2float(hb));
    }
    *(uint4*)(th + (size_t)n * Kd + k0) = *(uint4*)hh;
    *(uint4*)(tl + (size_t)n * Kd + k0) = *(uint4*)ll;
}

// ---------------------------------------------------------------------------
// fp16 B-split GEMM (R12-proven): BM=128 BN=64 BK=32, 8 warps, 3-stage
// cp.async pipeline, LDSM fragments, row stride 80B, 61.4KB smem, 2 CTA/SM.
// MODE 0: KV -> g_Kh / g_Vt   MODE 1: Q -> g_Qh (xQSCALE)   MODE 2: fp32 out
// ---------------------------------------------------------------------------
extern __shared__ char dynsm[];

#define G2BUF 20480
#define A2    0
#define B2H   10240
#define B2L   15360

template<int MODE>
__global__ void __launch_bounds__(256, 2) gemm_fp16(
    const __half* __restrict__ A, const __half* __restrict__ Bh,
    const __half* __restrict__ Bl, const float* __restrict__ bias,
    float* __restrict__ out, int Ntot)
{
    const int tid = threadIdx.x, lane = tid & 31, warp = tid >> 5;
    const int wm = (warp >> 1) * 32, wn = (warp & 1) * 32;
    const int m0 = blockIdx.y * 128, n0 = blockIdx.x * 64;

    const __half* ag  = A  + (size_t)m0 * K_;
    const __half* bgh = Bh + (size_t)n0 * K_;
    const __half* bgl = Bl + (size_t)n0 * K_;

    const int ra = tid >> 1, ga = tid & 1;
    const int t2 = tid & 127;
    const int rb = t2 >> 1, gb = t2 & 1;
    const __half* bsrc = (tid < 128) ? bgh : bgl;
    const int bofs = (tid < 128) ? B2H : B2L;

    auto issue_loads = [&](int kc, int buf) {
        char* bb = dynsm + buf * G2BUF;
        const __half* sa = ag + (size_t)ra * K_ + kc * 32 + ga * 16;
        const __half* sb = bsrc + (size_t)rb * K_ + kc * 32 + gb * 16;
        cp16(bb + A2 + ra * 80 + ga * 32,      sa);
        cp16(bb + A2 + ra * 80 + ga * 32 + 16, sa + 8);
        cp16(bb + bofs + rb * 80 + gb * 32,      sb);
        cp16(bb + bofs + rb * 80 + gb * 32 + 16, sb + 8);
    };

    float4 acc[2][4];
    #pragma unroll
    for (int mt = 0; mt < 2; mt++)
        #pragma unroll
        for (int nt = 0; nt < 4; nt++) acc[mt][nt] = make_float4(0.f, 0.f, 0.f, 0.f);

    issue_loads(0, 0); CP_COMMIT();
    issue_loads(1, 1); CP_COMMIT();

    const uint32_t smb = smem_u32(dynsm);
    const uint32_t a_off = (uint32_t)(lane & 15) * 80 + 16 * (lane >> 4);
    const uint32_t b_off = (uint32_t)(8 * (lane >> 4) + (lane & 7)) * 80
                         + 16 * ((lane >> 3) & 1);

    #pragma unroll 1
    for (int kc = 0; kc < 32; kc++) {
        if (kc < 31) CP_WAIT(1); else CP_WAIT(0);
        __syncthreads();
        if (kc + 2 < 32) { issue_loads(kc + 2, (kc + 2) % 3); CP_COMMIT(); }

        const uint32_t bufb = smb + (kc % 3) * G2BUF;
        #pragma unroll
        for (int ks = 0; ks < 2; ks++) {
            const uint32_t kso = ks * 32;
            unsigned a[2][4];
            #pragma unroll
            for (int mt = 0; mt < 2; mt++)
                ldsm4(a[mt][0], a[mt][1], a[mt][2], a[mt][3],
                      bufb + A2 + (uint32_t)(wm + mt * 16) * 80 + a_off + kso);
            #pragma unroll
            for (int ntp = 0; ntp < 2; ntp++) {
                const uint32_t nrow = (uint32_t)(wn + 16 * ntp) * 80 + b_off + kso;
                unsigned h0, h1, h2, h3, l0, l1, l2, l3;
                ldsm4(h0, h1, h2, h3, bufb + B2H + nrow);
                ldsm4(l0, l1, l2, l3, bufb + B2L + nrow);
                #pragma unroll
                for (int mt = 0; mt < 2; mt++) {
                    mma16h(acc[mt][2*ntp],   a[mt][0], a[mt][1], a[mt][2], a[mt][3], h0, h1);
                    mma16h(acc[mt][2*ntp],   a[mt][0], a[mt][1], a[mt][2], a[mt][3], l0, l1);
                    mma16h(acc[mt][2*ntp+1], a[mt][0], a[mt][1], a[mt][2], a[mt][3], h2, h3);
                    mma16h(acc[mt][2*ntp+1], a[mt][0], a[mt][1], a[mt][2], a[mt][3], l2, l3);
                }
            }
        }
    }

    // ---- epilogue ----
    const int r = lane >> 2, q = lane & 3;
    #pragma unroll
    for (int mt = 0; mt < 2; mt++) {
        #pragma unroll
        for (int nt = 0; nt < 4; nt++) {
            int mg = m0 + wm + mt * 16 + r;
            int ng = n0 + wn + nt * 8 + 2 * q;
            float bv0 = bias[ng], bv1 = bias[ng + 1];
            float2 v0 = {acc[mt][nt].x + bv0, acc[mt][nt].y + bv1};
            float2 v1 = {acc[mt][nt].z + bv0, acc[mt][nt].w + bv1};
            if (MODE == 1) {
                v0.x *= QSCALE; v0.y *= QSCALE;
                v1.x *= QSCALE; v1.y *= QSCALE;
            }
            #pragma unroll
            for (int rr = 0; rr < 2; rr++) {
                int m = mg + rr * 8;
                float2 v = rr ? v1 : v0;
                if (MODE == 0) {
                    int bi = m >> 11, s = m & (S_-1);
                    int h = ng >> 7, c = ng & 127;
                    if (c < 64) {
                        __half2 hv = __floats2half2_rn(v.x, v.y);
                        *(__half2*)(g_Kh + (((size_t)(bi*H_ + h) * S_ + s) * HD_ + c)) = hv;
                    } else {
                        int d = c - 64;
                        size_t base = ((size_t)(bi*H_ + h) * HD_ + d) * S_ + s;
                        g_Vt[base]      = __float2half_rn(v.x);
                        g_Vt[base + S_] = __float2half_rn(v.y);
                    }
                } else if (MODE == 1) {
                    int bi = m >> 11, s = m & (S_-1);
                    int h = ng >> 6, d = ng & 63;
                    __half2 hv = __floats2half2_rn(v.x, v.y);
                    *(__half2*)(g_Qh + (((size_t)(bi*H_ + h) * S_ + s) * HD_ + d)) = hv;
                } else {
                    *(float2*)(out + (size_t)m * Ntot + ng) = v;
                }
            }
        }
    }
}

// ---------------------------------------------------------------------------
// Flash attention (R12 structure), fp16 m16n8k16, base-2 fixed-shift softmax:
// p = ex2(s + m')  where Q pre-scaled by 0.125*log2e and m' = m*log2e.
// 128-row q tiles, 8 warps, double-buffered K/V, 2 CTAs/SM.
// ---------------------------------------------------------------------------
#define SQH 72
#define SKH 72
#define SVH 72

__global__ void __launch_bounds__(256, 2) attn_fp16(
    const __half* __restrict__ gK, const __half* __restrict__ gVt,
    const __half* __restrict__ gQ, const float* __restrict__ msc,
    __half* __restrict__ ctx)
{
    __half* smh = (__half*)dynsm;
    __half* Qs  = smh;                      // [128][SQH]
    __half* Kb  = Qs + 128 * SQH;           // 2 x [64][SKH]
    __half* Vb  = Kb + 2 * 64 * SKH;        // 2 x [64][SVH]

    const int tid  = threadIdx.x;
    const int lane = tid & 31;
    const int w    = tid >> 5;
    const int ib   = w * 16;
    const int q0   = blockIdx.x * 128;
    const int h    = blockIdx.y;
    const int b    = blockIdx.z;

    const __half* Qg = gQ  + ((size_t)(b*H_ + h) * S_ + q0) * HD_;
    const __half* Kg = gK  + ((size_t)(b*H_ + h) * S_) * HD_;
    const __half* Vg = gVt + ((size_t)(b*H_ + h) * HD_) * S_;

    // Q tile
    {
        int r = tid >> 1, cs = (tid & 1) * 32;
        const __half* src = Qg + (size_t)r * HD_ + cs;
        __half* dst = Qs + r * SQH + cs;
        cp16(dst,      src);
        cp16(dst + 8,  src + 8);
        cp16(dst + 16, src + 16);
        cp16(dst + 24, src + 24);
    }

    const int rKV = tid >> 2;
    const int seg = (tid & 3) * 16;

    auto issue = [&](int kt, int buf) {
        __half* Kd = Kb + buf * 64 * SKH;
        __half* Vd = Vb + buf * 64 * SVH;
        const __half* ks = Kg + (size_t)(kt*64 + rKV) * HD_ + seg;
        const __half* vs = Vg + (size_t)rKV * S_ + kt*64 + seg;
        cp16(Kd + rKV * SKH + seg,     ks);
        cp16(Kd + rKV * SKH + seg + 8, ks + 8);
        cp16(Vd + rKV * SVH + seg,     vs);
        cp16(Vd + rKV * SVH + seg + 8, vs + 8);
    };

    float4 o[8];
    #pragma unroll
    for (int nt = 0; nt < 8; nt++) o[nt] = make_float4(0.f, 0.f, 0.f, 0.f);
    float l0r = 0.f, l1r = 0.f;

    const int r  = lane >> 2;
    const int qd = lane & 3;
    const int grow0 = ib + r;
    const int grow1 = grow0 + 8;
    const float* mrow0 = msc + (size_t)(q0 + grow0) * S_ + 2 * qd;
    const float* mrow1 = msc + (size_t)(q0 + grow1) * S_ + 2 * qd;

    // LDSM per-lane byte offsets
    const uint32_t qs_b = smem_u32(Qs);
    const uint32_t kb_b = smem_u32(Kb);
    const uint32_t vb_b = smem_u32(Vb);
    const uint32_t q_off = ((uint32_t)(ib + (lane & 15)) * SQH) * 2 + 16 * (lane >> 4);
    const uint32_t k_row = ((uint32_t)(8 * (lane >> 4) + (lane & 7)) * SKH) * 2
                         + 16 * ((lane >> 3) & 1);
    const uint32_t v_row = ((uint32_t)(8 * (lane >> 4) + (lane & 7)) * SVH) * 2
                         + 16 * ((lane >> 3) & 1);

    issue(0, 0); CP_COMMIT();

    #pragma unroll 1
    for (int kt = 0; kt < S_/64; kt++) {
        const int cur = kt & 1;
        CP_WAIT(0);
        __syncthreads();
        if (kt + 1 < S_/64) { issue(kt + 1, cur ^ 1); CP_COMMIT(); }

        float2 mreg[16];
        #pragma unroll
        for (int nt = 0; nt < 8; nt++) {
            mreg[2*nt]   = *(const float2*)(mrow0 + kt * 64 + nt * 8);
            mreg[2*nt+1] = *(const float2*)(mrow1 + kt * 64 + nt * 8);
        }

        const uint32_t ksb = kb_b + cur * (64 * SKH * 2);
        const uint32_t vsb = vb_b + cur * (64 * SVH * 2);

        // --- S = Q K^T ---
        float4 s[8];
        #pragma unroll
        for (int nt = 0; nt < 8; nt++) s[nt] = make_float4(0.f, 0.f, 0.f, 0.f);
        #pragma unroll
        for (int kc = 0; kc < 4; kc++) {
            unsigned a0, a1, a2, a3;
            ldsm4(a0, a1, a2, a3, qs_b + q_off + 32 * kc);
            #pragma unroll
            for (int ntp = 0; ntp < 4; ntp++) {
                unsigned b0, b1, b2, b3;
                ldsm4(b0, b1, b2, b3,
                      ksb + (uint32_t)(16 * ntp) * (SKH * 2) + k_row + 32 * kc);
                mma16h(s[2*ntp],   a0, a1, a2, a3, b0, b1);
                mma16h(s[2*ntp+1], a0, a1, a2, a3, b2, b3);
            }
        }

        // --- base-2 fixed-shift softmax: p = ex2(s + m') (MUFU pipe) ---
        unsigned pa0[8], pa1[8];
        #pragma unroll
        for (int nt = 0; nt < 8; nt++) {
            float p00 = ex2(s[nt].x + mreg[2*nt].x);
            float p01 = ex2(s[nt].y + mreg[2*nt].y);
            float p10 = ex2(s[nt].z + mreg[2*nt+1].x);
            float p11 = ex2(s[nt].w + mreg[2*nt+1].y);
            l0r += p00 + p01;
            l1r += p10 + p11;
            __half2 h0 = __floats2half2_rn(p00, p01);
            __half2 h1 = __floats2half2_rn(p10, p11);
            pa0[nt] = *(unsigned*)&h0;
            pa1[nt] = *(unsigned*)&h1;
        }

        // --- O += P V ---
        #pragma unroll
        for (int kc = 0; kc < 4; kc++) {
            unsigned a0 = pa0[2*kc];
            unsigned a1 = pa1[2*kc];
            unsigned a2 = pa0[2*kc + 1];
            unsigned a3 = pa1[2*kc + 1];
            #pragma unroll
            for (int ntp = 0; ntp < 4; ntp++) {
                unsigned b0, b1, b2, b3;
                ldsm4(b0, b1, b2, b3,
                      vsb + (uint32_t)(16 * ntp) * (SVH * 2) + v_row + 32 * kc);
                mma16h(o[2*ntp],   a0, a1, a2, a3, b0, b1);
                mma16h(o[2*ntp+1], a0, a1, a2, a3, b2, b3);
            }
        }
    }

    // row-sum reduction + normalize + fp16 ctx store
    l0r += __shfl_xor_sync(0xffffffffu, l0r, 1);
    l0r += __shfl_xor_sync(0xffffffffu, l0r, 2);
    l1r += __shfl_xor_sync(0xffffffffu, l1r, 1);
    l1r += __shfl_xor_sync(0xffffffffu, l1r, 2);
    float inv0 = 1.f / l0r;
    float inv1 = 1.f / l1r;
    int gq = q0 + grow0;
    #pragma unroll
    for (int nt = 0; nt < 8; nt++) {
        int dcol = h * HD_ + nt * 8 + 2 * qd;
        size_t i0 = ((size_t)b * S_ + gq) * D_ + dcol;
        size_t i1 = ((size_t)b * S_ + gq + 8) * D_ + dcol;
        __half2 h0 = __floats2half2_rn(o[nt].x * inv0, o[nt].y * inv0);
        __half2 h1 = __floats2half2_rn(o[nt].z * inv1, o[nt].w * inv1);
        *(__half2*)&ctx[i0] = h0;
        *(__half2*)&ctx[i1] = h1;
    }
}

// ---------------------------------------------------------------------------
extern "C" void kernel_launch(void* const* d_in, const int* in_sizes, int n_in,
                              void* d_out, int out_size)
{
    const float* x    = (const float*)d_in[0];
    const float* y    = (const float*)d_in[1];
    const float* mask = (const float*)d_in[2];
    const float* Wkv  = (const float*)d_in[3];
    const float* bkv  = (const float*)d_in[4];
    const float* Wq   = (const float*)d_in[5];
    const float* bq   = (const float*)d_in[6];
    const float* Wo   = (const float*)d_in[7];
    const float* bo   = (const float*)d_in[8];
    float* out = (float*)d_out;

    __half *pKh, *pVt, *pQh, *pCtx, *pxf, *pyf;
    float *pMsc;
    __half *pWkvh, *pWkvl, *pWqh, *pWql, *pWoh, *pWol;
    cudaGetSymbolAddress((void**)&pKh, g_Kh);
    cudaGetSymbolAddress((void**)&pVt, g_Vt);
    cudaGetSymbolAddress((void**)&pQh, g_Qh);
    cudaGetSymbolAddress((void**)&pCtx, g_ctx);
    cudaGetSymbolAddress((void**)&pxf, g_xf);
    cudaGetSymbolAddress((void**)&pyf, g_yf);
    cudaGetSymbolAddress((void**)&pMsc, g_msc);
    cudaGetSymbolAddress((void**)&pWkvh, g_Wkvh); cudaGetSymbolAddress((void**)&pWkvl, g_Wkvl);
    cudaGetSymbolAddress((void**)&pWqh, g_Wqh);   cudaGetSymbolAddress((void**)&pWql, g_Wql);
    cudaGetSymbolAddress((void**)&pWoh, g_Woh);   cudaGetSymbolAddress((void**)&pWol, g_Wol);

    const int GSM = 3 * G2BUF;                                  // 61440 B
    const int ASM = (128*SQH + 2*64*SKH + 2*64*SVH) * 2;        // 55296 B
    cudaFuncSetAttribute(gemm_fp16<0>, cudaFuncAttributeMaxDynamicSharedMemorySize, GSM);
    cudaFuncSetAttribute(gemm_fp16<1>, cudaFuncAttributeMaxDynamicSharedMemorySize, GSM);
    cudaFuncSetAttribute(gemm_fp16<2>, cudaFuncAttributeMaxDynamicSharedMemorySize, GSM);
    cudaFuncSetAttribute(attn_fp16, cudaFuncAttributeMaxDynamicSharedMemorySize, ASM);

    const int NE4 = B_ * S_ * D_ / 4;
    const int NM4 = S_ * S_ / 4;

    // 1. converts / weight splits / mask pre-scale
    to_half<<<(NE4 + 255) / 256, 256>>>(x, pxf, NE4);
    to_half<<<(NE4 + 255) / 256, 256>>>(y, pyf, NE4);
    scale_mask<<<(NM4 + 255) / 256, 256>>>(mask, pMsc, NM4);
    split_transpose_h<<<dim3(2*D_/32, K_/64), 256>>>(Wkv, pWkvh, pWkvl, K_, 2*D_);
    split_transpose_h<<<dim3(D_/32,   K_/64), 256>>>(Wq,  pWqh,  pWql,  K_, D_);
    split_transpose_h<<<dim3(D_/32,   K_/64), 256>>>(Wo,  pWoh,  pWol,  K_, D_);
    // 2. KV projection: M=8192, N=2048
    gemm_fp16<0><<<dim3(2048/64, 8192/128), 256, GSM>>>(pxf, pWkvh, pWkvl, bkv, nullptr, 2*D_);
    // 3. Q projection: M=8192, N=1024 (Q pre-scaled by 0.125*log2e)
    gemm_fp16<1><<<dim3(1024/64, 8192/128), 256, GSM>>>(pyf, pWqh, pWql, bq, nullptr, D_);
    // 4. attention (base-2 softmax; writes fp16 ctx)
    attn_fp16<<<dim3(S_/128, H_, B_), 256, ASM>>>(pKh, pVt, pQh, pMsc, pCtx);
    // 5. O projection: M=8192, N=1024
    gemm_fp16<2><<<dim3(1024/64, 8192/128), 256, GSM>>>(pCtx, pWoh, pWol, bo, out, D_);
}

// round 16
// speedup vs baseline: 1.2193x; 1.1638x over previous
#include <cuda_runtime.h>
#include <cuda_fp16.h>
#include <math.h>
#include <stdint.h>

#define B_  4
#define S_  2048
#define D_  1024
#define H_  16
#define HD_ 64
#define K_  1024

// Q pre-scale: 0.125 * log2(e)  (folded softmax scale + base-2 conversion)
#define QSCALE 0.18033688011112042f
// mask pre-scale: log2(e)
#define MSCALE 1.4426950408889634f

// fp16 intermediates
__device__ __align__(16) __half g_Kh[B_*H_*S_*HD_];   // [b][h][s][d]
__device__ __align__(16) __half g_Vt[B_*H_*HD_*S_];   // [b][h][d][s]  (transposed)
__device__ __align__(16) __half g_Qh[B_*H_*S_*HD_];   // [b][h][s][d]  (pre-scaled)
__device__ __align__(16) __half g_ctx[B_*S_*D_];      // attention out (fp16)
__device__ __align__(16) float  g_msc[S_*S_];         // mask * log2(e), fp32

// fp16 activations (single) + fp16 hi/lo weights (transposed [N][K])
__device__ __align__(16) __half g_xf[B_*S_*D_], g_yf[B_*S_*D_];
__device__ __align__(16) __half g_Wkvh[2*D_*D_], g_Wkvl[2*D_*D_];
__device__ __align__(16) __half g_Wqh[D_*D_],  g_Wql[D_*D_];
__device__ __align__(16) __half g_Woh[D_*D_],  g_Wol[D_*D_];

// ---------------------------------------------------------------------------
// helpers
// ---------------------------------------------------------------------------
__device__ __forceinline__ uint32_t smem_u32(const void* p) {
    uint32_t a;
    asm("{ .reg .u64 t; cvta.to.shared.u64 t, %1; cvt.u32.u64 %0, t; }" : "=r"(a) : "l"(p));
    return a;
}
__device__ __forceinline__ void cp16(void* dst, const void* src) {
    uint32_t d = smem_u32(dst);
    asm volatile("cp.async.cg.shared.global [%0], [%1], 16;" :: "r"(d), "l"(src) : "memory");
}
#define CP_COMMIT() asm volatile("cp.async.commit_group;" ::: "memory")
#define CP_WAIT(n)  asm volatile("cp.async.wait_group %0;" :: "n"(n) : "memory")

// ldmatrix x4
__device__ __forceinline__ void ldsm4(unsigned& r0, unsigned& r1,
                                      unsigned& r2, unsigned& r3, uint32_t addr)
{
    asm volatile("ldmatrix.sync.aligned.m8n8.x4.shared.b16 {%0,%1,%2,%3}, [%4];"
        : "=r"(r0), "=r"(r1), "=r"(r2), "=r"(r3) : "r"(addr));
}

// fp16 mma
__device__ __forceinline__ void mma16h(float4& d,
    unsigned a0, unsigned a1, unsigned a2, unsigned a3, unsigned b0, unsigned b1)
{
    asm volatile("mma.sync.aligned.m16n8k16.row.col.f32.f16.f16.f32 "
        "{%0,%1,%2,%3},{%4,%5,%6,%7},{%8,%9},{%0,%1,%2,%3};\n"
        : "+f"(d.x), "+f"(d.y), "+f"(d.z), "+f"(d.w)
        : "r"(a0), "r"(a1), "r"(a2), "r"(a3), "r"(b0), "r"(b1));
}
// MUFU exp2 (inputs already in base-2 domain)
__device__ __forceinline__ float ex2(float x) {
    float r;
    asm("ex2.approx.f32 %0, %1;" : "=f"(r) : "f"(x));
    return r;
}

// ---------------------------------------------------------------------------
// converts
// ---------------------------------------------------------------------------
__global__ void __launch_bounds__(256) to_half(const float* __restrict__ src,
    __half* __restrict__ dst, int n4)
{
    int i = blockIdx.x * 256 + threadIdx.x;
    if (i >= n4) return;
    float4 v = ((const float4*)src)[i];
    __half2 h01 = __floats2half2_rn(v.x, v.y);
    __half2 h23 = __floats2half2_rn(v.z, v.w);
    uint2 hv = { *(unsigned*)&h01, *(unsigned*)&h23 };
    *(uint2*)(dst + 4 * (size_t)i) = hv;
}

__global__ void __launch_bounds__(256) scale_mask(const float* __restrict__ src,
    float* __restrict__ dst, int n4)
{
    int i = blockIdx.x * 256 + threadIdx.x;
    if (i >= n4) return;
    float4 v = ((const float4*)src)[i];
    v.x *= MSCALE; v.y *= MSCALE; v.z *= MSCALE; v.w *= MSCALE;
    ((float4*)dst)[i] = v;
}

__global__ void __launch_bounds__(256) split_transpose_h(const float* __restrict__ W,
    __half* __restrict__ th, __half* __restrict__ tl, int Kd, int Nd)
{
    int n  = blockIdx.x * 32 + (threadIdx.x & 31);
    int k0 = blockIdx.y * 64 + (threadIdx.x >> 5) * 8;
    __half hh[8], ll[8];
    #pragma unroll
    for (int j = 0; j < 8; j++) {
        float v = W[(size_t)(k0 + j) * Nd + n];
        __half hb = __float2half_rn(v);
        hh[j] = hb;
        ll[j] = __float2half_rn(v - __half2float(hb));
    }
    *(uint4*)(th + (size_t)n * Kd + k0) = *(uint4*)hh;
    *(uint4*)(tl + (size_t)n * Kd + k0) = *(uint4*)ll;
}

// ---------------------------------------------------------------------------
// fp16 GEMM: C = A_fp16 @ W^T + bias.  NS=2: B-split (Wh+Wl, 2 MMAs/k-tile);
// NS=1: single fp16 weights (1 MMA/k-tile, half the B loads).
// BM=128 BN=64 BK=32, 8 warps, 3-stage cp.async pipeline, LDSM fragments.
// Row stride 80B. 61.4KB smem -> 2 CTA/SM.
// MODE 0: KV -> g_Kh / g_Vt   MODE 1: Q -> g_Qh (xQSCALE)   MODE 2: fp32 out
// ---------------------------------------------------------------------------
extern __shared__ char dynsm[];

#define G2BUF 20480
#define A2    0
#define B2H   10240
#define B2L   15360

template<int MODE, int NS>
__global__ void __launch_bounds__(256, 2) gemm_fp16(
    const __half* __restrict__ A, const __half* __restrict__ Bh,
    const __half* __restrict__ Bl, const float* __restrict__ bias,
    float* __restrict__ out, int Ntot)
{
    const int tid = threadIdx.x, lane = tid & 31, warp = tid >> 5;
    const int wm = (warp >> 1) * 32, wn = (warp & 1) * 32;
    const int m0 = blockIdx.y * 128, n0 = blockIdx.x * 64;

    const __half* ag  = A  + (size_t)m0 * K_;
    const __half* bgh = Bh + (size_t)n0 * K_;
    const __half* bgl = (NS == 2) ? (Bl + (size_t)n0 * K_) : nullptr;

    const int ra = tid >> 1, ga = tid & 1;
    // NS==2: threads<128 -> Bh, >=128 -> Bl (2 cp16 each)
    // NS==1: all 256 threads cover Bh at 16B granularity (1 cp16 each)
    const int t2 = tid & 127;
    const int rb2 = t2 >> 1, gb2 = t2 & 1;
    const __half* bsrc2 = (tid < 128) ? bgh : bgl;
    const int bofs2 = (tid < 128) ? B2H : B2L;
    const int rb1 = tid >> 2, gb1 = (tid & 3) * 16;   // bytes within 64B row

    auto issue_loads = [&](int kc, int buf) {
        char* bb = dynsm + buf * G2BUF;
        const __half* sa = ag + (size_t)ra * K_ + kc * 32 + ga * 16;
        cp16(bb + A2 + ra * 80 + ga * 32,      sa);
        cp16(bb + A2 + ra * 80 + ga * 32 + 16, sa + 8);
        if (NS == 2) {
            const __half* sb = bsrc2 + (size_t)rb2 * K_ + kc * 32 + gb2 * 16;
            cp16(bb + bofs2 + rb2 * 80 + gb2 * 32,      sb);
            cp16(bb + bofs2 + rb2 * 80 + gb2 * 32 + 16, sb + 8);
        } else {
            const __half* sb = bgh + (size_t)rb1 * K_ + kc * 32 + (gb1 >> 1);
            cp16(bb + B2H + rb1 * 80 + gb1, sb);
        }
    };

    float4 acc[2][4];
    #pragma unroll
    for (int mt = 0; mt < 2; mt++)
        #pragma unroll
        for (int nt = 0; nt < 4; nt++) acc[mt][nt] = make_float4(0.f, 0.f, 0.f, 0.f);

    issue_loads(0, 0); CP_COMMIT();
    issue_loads(1, 1); CP_COMMIT();

    const uint32_t smb = smem_u32(dynsm);
    const uint32_t a_off = (uint32_t)(lane & 15) * 80 + 16 * (lane >> 4);
    const uint32_t b_off = (uint32_t)(8 * (lane >> 4) + (lane & 7)) * 80
                         + 16 * ((lane >> 3) & 1);

    #pragma unroll 1
    for (int kc = 0; kc < 32; kc++) {
        if (kc < 31) CP_WAIT(1); else CP_WAIT(0);
        __syncthreads();
        if (kc + 2 < 32) { issue_loads(kc + 2, (kc + 2) % 3); CP_COMMIT(); }

        const uint32_t bufb = smb + (kc % 3) * G2BUF;
        #pragma unroll
        for (int ks = 0; ks < 2; ks++) {
            const uint32_t kso = ks * 32;
            unsigned a[2][4];
            #pragma unroll
            for (int mt = 0; mt < 2; mt++)
                ldsm4(a[mt][0], a[mt][1], a[mt][2], a[mt][3],
                      bufb + A2 + (uint32_t)(wm + mt * 16) * 80 + a_off + kso);
            #pragma unroll
            for (int ntp = 0; ntp < 2; ntp++) {
                const uint32_t nrow = (uint32_t)(wn + 16 * ntp) * 80 + b_off + kso;
                unsigned h0, h1, h2, h3;
                ldsm4(h0, h1, h2, h3, bufb + B2H + nrow);
                if (NS == 2) {
                    unsigned l0, l1, l2, l3;
                    ldsm4(l0, l1, l2, l3, bufb + B2L + nrow);
                    #pragma unroll
                    for (int mt = 0; mt < 2; mt++) {
                        mma16h(acc[mt][2*ntp],   a[mt][0], a[mt][1], a[mt][2], a[mt][3], h0, h1);
                        mma16h(acc[mt][2*ntp],   a[mt][0], a[mt][1], a[mt][2], a[mt][3], l0, l1);
                        mma16h(acc[mt][2*ntp+1], a[mt][0], a[mt][1], a[mt][2], a[mt][3], h2, h3);
                        mma16h(acc[mt][2*ntp+1], a[mt][0], a[mt][1], a[mt][2], a[mt][3], l2, l3);
                    }
                } else {
                    #pragma unroll
                    for (int mt = 0; mt < 2; mt++) {
                        mma16h(acc[mt][2*ntp],   a[mt][0], a[mt][1], a[mt][2], a[mt][3], h0, h1);
                        mma16h(acc[mt][2*ntp+1], a[mt][0], a[mt][1], a[mt][2], a[mt][3], h2, h3);
                    }
                }
            }
        }
    }

    // ---- epilogue ----
    const int r = lane >> 2, q = lane & 3;
    #pragma unroll
    for (int mt = 0; mt < 2; mt++) {
        #pragma unroll
        for (int nt = 0; nt < 4; nt++) {
            int mg = m0 + wm + mt * 16 + r;
            int ng = n0 + wn + nt * 8 + 2 * q;
            float bv0 = bias[ng], bv1 = bias[ng + 1];
            float2 v0 = {acc[mt][nt].x + bv0, acc[mt][nt].y + bv1};
            float2 v1 = {acc[mt][nt].z + bv0, acc[mt][nt].w + bv1};
            if (MODE == 1) {
                v0.x *= QSCALE; v0.y *= QSCALE;
                v1.x *= QSCALE; v1.y *= QSCALE;
            }
            #pragma unroll
            for (int rr = 0; rr < 2; rr++) {
                int m = mg + rr * 8;
                float2 v = rr ? v1 : v0;
                if (MODE == 0) {
                    int bi = m >> 11, s = m & (S_-1);
                    int h = ng >> 7, c = ng & 127;
                    if (c < 64) {
                        __half2 hv = __floats2half2_rn(v.x, v.y);
                        *(__half2*)(g_Kh + (((size_t)(bi*H_ + h) * S_ + s) * HD_ + c)) = hv;
                    } else {
                        int d = c - 64;
                        size_t base = ((size_t)(bi*H_ + h) * HD_ + d) * S_ + s;
                        g_Vt[base]      = __float2half_rn(v.x);
                        g_Vt[base + S_] = __float2half_rn(v.y);
                    }
                } else if (MODE == 1) {
                    int bi = m >> 11, s = m & (S_-1);
                    int h = ng >> 6, d = ng & 63;
                    __half2 hv = __floats2half2_rn(v.x, v.y);
                    *(__half2*)(g_Qh + (((size_t)(bi*H_ + h) * S_ + s) * HD_ + d)) = hv;
                } else {
                    *(float2*)(out + (size_t)m * Ntot + ng) = v;
                }
            }
        }
    }
}

// ---------------------------------------------------------------------------
// Flash attention (R15-proven): fp16 m16n8k16, base-2 fixed-shift softmax
// p = ex2(s + m'); 128-row q tiles, 8 warps, double-buffered K/V, 2 CTAs/SM.
// ---------------------------------------------------------------------------
#define SQH 72
#define SKH 72
#define SVH 72

__global__ void __launch_bounds__(256, 2) attn_fp16(
    const __half* __restrict__ gK, const __half* __restrict__ gVt,
    const __half* __restrict__ gQ, const float* __restrict__ msc,
    __half* __restrict__ ctx)
{
    __half* smh = (__half*)dynsm;
    __half* Qs  = smh;                      // [128][SQH]
    __half* Kb  = Qs + 128 * SQH;           // 2 x [64][SKH]
    __half* Vb  = Kb + 2 * 64 * SKH;        // 2 x [64][SVH]

    const int tid  = threadIdx.x;
    const int lane = tid & 31;
    const int w    = tid >> 5;
    const int ib   = w * 16;
    const int q0   = blockIdx.x * 128;
    const int h    = blockIdx.y;
    const int b    = blockIdx.z;

    const __half* Qg = gQ  + ((size_t)(b*H_ + h) * S_ + q0) * HD_;
    const __half* Kg = gK  + ((size_t)(b*H_ + h) * S_) * HD_;
    const __half* Vg = gVt + ((size_t)(b*H_ + h) * HD_) * S_;

    // Q tile
    {
        int r = tid >> 1, cs = (tid & 1) * 32;
        const __half* src = Qg + (size_t)r * HD_ + cs;
        __half* dst = Qs + r * SQH + cs;
        cp16(dst,      src);
        cp16(dst + 8,  src + 8);
        cp16(dst + 16, src + 16);
        cp16(dst + 24, src + 24);
    }

    const int rKV = tid >> 2;
    const int seg = (tid & 3) * 16;

    auto issue = [&](int kt, int buf) {
        __half* Kd = Kb + buf * 64 * SKH;
        __half* Vd = Vb + buf * 64 * SVH;
        const __half* ks = Kg + (size_t)(kt*64 + rKV) * HD_ + seg;
        const __half* vs = Vg + (size_t)rKV * S_ + kt*64 + seg;
        cp16(Kd + rKV * SKH + seg,     ks);
        cp16(Kd + rKV * SKH + seg + 8, ks + 8);
        cp16(Vd + rKV * SVH + seg,     vs);
        cp16(Vd + rKV * SVH + seg + 8, vs + 8);
    };

    float4 o[8];
    #pragma unroll
    for (int nt = 0; nt < 8; nt++) o[nt] = make_float4(0.f, 0.f, 0.f, 0.f);
    float l0r = 0.f, l1r = 0.f;

    const int r  = lane >> 2;
    const int qd = lane & 3;
    const int grow0 = ib + r;
    const int grow1 = grow0 + 8;
    const float* mrow0 = msc + (size_t)(q0 + grow0) * S_ + 2 * qd;
    const float* mrow1 = msc + (size_t)(q0 + grow1) * S_ + 2 * qd;

    // LDSM per-lane byte offsets
    const uint32_t qs_b = smem_u32(Qs);
    const uint32_t kb_b = smem_u32(Kb);
    const uint32_t vb_b = smem_u32(Vb);
    const uint32_t q_off = ((uint32_t)(ib + (lane & 15)) * SQH) * 2 + 16 * (lane >> 4);
    const uint32_t k_row = ((uint32_t)(8 * (lane >> 4) + (lane & 7)) * SKH) * 2
                         + 16 * ((lane >> 3) & 1);
    const uint32_t v_row = ((uint32_t)(8 * (lane >> 4) + (lane & 7)) * SVH) * 2
                         + 16 * ((lane >> 3) & 1);

    issue(0, 0); CP_COMMIT();

    #pragma unroll 1
    for (int kt = 0; kt < S_/64; kt++) {
        const int cur = kt & 1;
        CP_WAIT(0);
        __syncthreads();
        if (kt + 1 < S_/64) { issue(kt + 1, cur ^ 1); CP_COMMIT(); }

        float2 mreg[16];
        #pragma unroll
        for (int nt = 0; nt < 8; nt++) {
            mreg[2*nt]   = *(const float2*)(mrow0 + kt * 64 + nt * 8);
            mreg[2*nt+1] = *(const float2*)(mrow1 + kt * 64 + nt * 8);
        }

        const uint32_t ksb = kb_b + cur * (64 * SKH * 2);
        const uint32_t vsb = vb_b + cur * (64 * SVH * 2);

        // --- S = Q K^T ---
        float4 s[8];
        #pragma unroll
        for (int nt = 0; nt < 8; nt++) s[nt] = make_float4(0.f, 0.f, 0.f, 0.f);
        #pragma unroll
        for (int kc = 0; kc < 4; kc++) {
            unsigned a0, a1, a2, a3;
            ldsm4(a0, a1, a2, a3, qs_b + q_off + 32 * kc);
            #pragma unroll
            for (int ntp = 0; ntp < 4; ntp++) {
                unsigned b0, b1, b2, b3;
                ldsm4(b0, b1, b2, b3,
                      ksb + (uint32_t)(16 * ntp) * (SKH * 2) + k_row + 32 * kc);
                mma16h(s[2*ntp],   a0, a1, a2, a3, b0, b1);
                mma16h(s[2*ntp+1], a0, a1, a2, a3, b2, b3);
            }
        }

        // --- base-2 fixed-shift softmax: p = ex2(s + m') ---
        unsigned pa0[8], pa1[8];
        #pragma unroll
        for (int nt = 0; nt < 8; nt++) {
            float p00 = ex2(s[nt].x + mreg[2*nt].x);
            float p01 = ex2(s[nt].y + mreg[2*nt].y);
            float p10 = ex2(s[nt].z + mreg[2*nt+1].x);
            float p11 = ex2(s[nt].w + mreg[2*nt+1].y);
            l0r += p00 + p01;
            l1r += p10 + p11;
            __half2 h0 = __floats2half2_rn(p00, p01);
            __half2 h1 = __floats2half2_rn(p10, p11);
            pa0[nt] = *(unsigned*)&h0;
            pa1[nt] = *(unsigned*)&h1;
        }

        // --- O += P V ---
        #pragma unroll
        for (int kc = 0; kc < 4; kc++) {
            unsigned a0 = pa0[2*kc];
            unsigned a1 = pa1[2*kc];
            unsigned a2 = pa0[2*kc + 1];
            unsigned a3 = pa1[2*kc + 1];
            #pragma unroll
            for (int ntp = 0; ntp < 4; ntp++) {
                unsigned b0, b1, b2, b3;
                ldsm4(b0, b1, b2, b3,
                      vsb + (uint32_t)(16 * ntp) * (SVH * 2) + v_row + 32 * kc);
                mma16h(o[2*ntp],   a0, a1, a2, a3, b0, b1);
                mma16h(o[2*ntp+1], a0, a1, a2, a3, b2, b3);
            }
        }
    }

    // row-sum reduction + normalize + fp16 ctx store
    l0r += __shfl_xor_sync(0xffffffffu, l0r, 1);
    l0r += __shfl_xor_sync(0xffffffffu, l0r, 2);
    l1r += __shfl_xor_sync(0xffffffffu, l1r, 1);
    l1r += __shfl_xor_sync(0xffffffffu, l1r, 2);
    float inv0 = 1.f / l0r;
    float inv1 = 1.f / l1r;
    int gq = q0 + grow0;
    #pragma unroll
    for (int nt = 0; nt < 8; nt++) {
        int dcol = h * HD_ + nt * 8 + 2 * qd;
        size_t i0 = ((size_t)b * S_ + gq) * D_ + dcol;
        size_t i1 = ((size_t)b * S_ + gq + 8) * D_ + dcol;
        __half2 h0 = __floats2half2_rn(o[nt].x * inv0, o[nt].y * inv0);
        __half2 h1 = __floats2half2_rn(o[nt].z * inv1, o[nt].w * inv1);
        *(__half2*)&ctx[i0] = h0;
        *(__half2*)&ctx[i1] = h1;
    }
}

// ---------------------------------------------------------------------------
extern "C" void kernel_launch(void* const* d_in, const int* in_sizes, int n_in,
                              void* d_out, int out_size)
{
    const float* x    = (const float*)d_in[0];
    const float* y    = (const float*)d_in[1];
    const float* mask = (const float*)d_in[2];
    const float* Wkv  = (const float*)d_in[3];
    const float* bkv  = (const float*)d_in[4];
    const float* Wq   = (const float*)d_in[5];
    const float* bq   = (const float*)d_in[6];
    const float* Wo   = (const float*)d_in[7];
    const float* bo   = (const float*)d_in[8];
    float* out = (float*)d_out;

    __half *pKh, *pVt, *pQh, *pCtx, *pxf, *pyf;
    float *pMsc;
    __half *pWkvh, *pWkvl, *pWqh, *pWql, *pWoh, *pWol;
    cudaGetSymbolAddress((void**)&pKh, g_Kh);
    cudaGetSymbolAddress((void**)&pVt, g_Vt);
    cudaGetSymbolAddress((void**)&pQh, g_Qh);
    cudaGetSymbolAddress((void**)&pCtx, g_ctx);
    cudaGetSymbolAddress((void**)&pxf, g_xf);
    cudaGetSymbolAddress((void**)&pyf, g_yf);
    cudaGetSymbolAddress((void**)&pMsc, g_msc);
    cudaGetSymbolAddress((void**)&pWkvh, g_Wkvh); cudaGetSymbolAddress((void**)&pWkvl, g_Wkvl);
    cudaGetSymbolAddress((void**)&pWqh, g_Wqh);   cudaGetSymbolAddress((void**)&pWql, g_Wql);
    cudaGetSymbolAddress((void**)&pWoh, g_Woh);   cudaGetSymbolAddress((void**)&pWol, g_Wol);

    const int GSM = 3 * G2BUF;                                  // 61440 B
    const int ASM = (128*SQH + 2*64*SKH + 2*64*SVH) * 2;        // 55296 B
    cudaFuncSetAttribute((const void*)gemm_fp16<0,1>, cudaFuncAttributeMaxDynamicSharedMemorySize, GSM);
    cudaFuncSetAttribute((const void*)gemm_fp16<1,1>, cudaFuncAttributeMaxDynamicSharedMemorySize, GSM);
    cudaFuncSetAttribute((const void*)gemm_fp16<2,2>, cudaFuncAttributeMaxDynamicSharedMemorySize, GSM);
    cudaFuncSetAttribute((const void*)attn_fp16, cudaFuncAttributeMaxDynamicSharedMemorySize, ASM);

    const int NE4 = B_ * S_ * D_ / 4;
    const int NM4 = S_ * S_ / 4;

    // 1. converts / weight splits / mask pre-scale
    to_half<<<(NE4 + 255) / 256, 256>>>(x, pxf, NE4);
    to_half<<<(NE4 + 255) / 256, 256>>>(y, pyf, NE4);
    scale_mask<<<(NM4 + 255) / 256, 256>>>(mask, pMsc, NM4);
    split_transpose_h<<<dim3(2*D_/32, K_/64), 256>>>(Wkv, pWkvh, pWkvl, K_, 2*D_);
    split_transpose_h<<<dim3(D_/32,   K_/64), 256>>>(Wq,  pWqh,  pWql,  K_, D_);
    split_transpose_h<<<dim3(D_/32,   K_/64), 256>>>(Wo,  pWoh,  pWol,  K_, D_);
    // 2. KV projection (single-fp16 weights): M=8192, N=2048
    gemm_fp16<0,1><<<dim3(2048/64, 8192/128), 256, GSM>>>(pxf, pWkvh, pWkvl, bkv, nullptr, 2*D_);
    // 3. Q projection (single-fp16 weights): M=8192, N=1024
    gemm_fp16<1,1><<<dim3(1024/64, 8192/128), 256, GSM>>>(pyf, pWqh, pWql, bq, nullptr, D_);
    // 4. attention (base-2 softmax; writes fp16 ctx)
    attn_fp16<<<dim3(S_/128, H_, B_), 256, ASM>>>(pKh, pVt, pQh, pMsc, pCtx);
    // 5. O projection (full B-split for output precision): M=8192, N=1024
    gemm_fp16<2,2><<<dim3(1024/64, 8192/128), 256, GSM>>>(pCtx, pWoh, pWol, bo, out, D_);
}